// round 14
// baseline (speedup 1.0000x reference)
#include <cuda_runtime.h>

#define FULL 0xffffffffu

constexpr int C    = 128;
constexpr int NMAX = 262144;

// ---------------- device scratch (static: no allocation allowed) ------------
__device__ float    g_loss[NMAX];
__device__ float    g_corr[NMAX];          // corr value if masked, -1.0f sentinel otherwise
__device__ double   g_kl_part[32];
__device__ double   g_loss_part[32];
__device__ double   g_clean_sum;
__device__ double   g_corr_sum;
__device__ unsigned long long g_cnt;
__device__ unsigned g_h1[2048], g_h2[2048], g_h3[1024];
__device__ unsigned g_b1, g_b12, g_key;
__device__ int      g_krem;
__device__ int      g_t64;                 // 1 if targets are int64
__device__ unsigned g_tick1, g_tick2, g_tick3, g_tick4;

// float -> order-preserving uint
__device__ __forceinline__ unsigned orderf(float f) {
    unsigned u = __float_as_uint(f);
    return (u & 0x80000000u) ? ~u : (u | 0x80000000u);
}

__device__ __forceinline__ int num_remember_dev(int epoch, int n) {
    double fr = fmin(0.5, (0.5 / 100.0) * (double)epoch);
    double rr = fmax(0.5, 1.0 - fr);
    return (int)(rr * (double)n);
}

// parallel "find bucket where cumsum crosses k" — call with 256 threads,
// NB buckets (multiple of 256). Exactly one thread hits the crossing.
template <int NB>
__device__ __forceinline__ void find_bucket(const unsigned* __restrict__ hist, int k,
                                            unsigned* out_b, int* out_krem) {
    __shared__ unsigned csum[256];
    constexpr int PER = NB / 256;
    int t = threadIdx.x;
    unsigned loc[PER];
    unsigned s = 0;
#pragma unroll
    for (int j = 0; j < PER; j++) { loc[j] = hist[t * PER + j]; s += loc[j]; }
    csum[t] = s;
    __syncthreads();
    // inclusive Hillis-Steele scan over 256 chunk sums
#pragma unroll
    for (int off = 1; off < 256; off <<= 1) {
        unsigned v = (t >= off) ? csum[t - off] : 0u;
        __syncthreads();
        csum[t] += v;
        __syncthreads();
    }
    unsigned prev = (t == 0) ? 0u : csum[t - 1];
    if (prev < (unsigned)k && csum[t] >= (unsigned)k) {
        unsigned cum = prev;
#pragma unroll
        for (int j = 0; j < PER; j++) {
            unsigned c = loc[j];
            if (cum + c >= (unsigned)k) { *out_b = (unsigned)(t * PER + j); *out_krem = k - (int)cum; break; }
            cum += c;
        }
    }
}

// returns true for the last block to arrive (block-uniform)
__device__ __forceinline__ bool last_block(unsigned* tick) {
    __threadfence();
    __shared__ bool isLast;
    if (threadIdx.x == 0) isLast = (atomicAdd(tick, 1u) == gridDim.x - 1);
    __syncthreads();
    return isLast;
}

// ---------------- K0: zero accumulators + detect int64 targets --------------
__global__ void k_init(const void* __restrict__ targ, int n) {
    int t = threadIdx.x;
    for (int i = t; i < 2048; i += 1024) g_h1[i] = 0;
    for (int i = t; i < 2048; i += 1024) g_h2[i] = 0;
    for (int i = t; i < 1024; i += 1024) g_h3[i] = 0;
    if (t < 32) { g_kl_part[t] = 0.0; g_loss_part[t] = 0.0; }
    if (t == 0) {
        g_clean_sum = 0.0; g_corr_sum = 0.0; g_cnt = 0ull;
        g_b1 = 0; g_b12 = 0; g_key = 0; g_krem = 1;
        g_tick1 = 0; g_tick2 = 0; g_tick3 = 0; g_tick4 = 0;
        const int* w = (const int*)targ;
        int nchk = (n >= 64) ? 32 : (n / 2);
        bool t64 = (nchk > 0);
        for (int j = 0; j < nchk; j++)
            if (w[2 * j + 1] != 0) { t64 = false; break; }
        g_t64 = t64 ? 1 : 0;
    }
}

// ---------------- K1: fused per-row stats + hist1 + (last block) scan1 ------
__global__ __launch_bounds__(256) void k_main(const float* __restrict__ y1,
                                              const float* __restrict__ y2,
                                              const void*  __restrict__ targ,
                                              const void*  __restrict__ ep,
                                              int n) {
    int row  = blockIdx.x * 8 + (threadIdx.x >> 5);
    int lane = threadIdx.x & 31;
    __shared__ double skl[8], sls[8];

    double kl_i = 0.0, lossd = 0.0;

    if (row < n) {
        const float4 av = ((const float4*)(y1 + (size_t)row * C))[lane];
        const float4 bv = ((const float4*)(y2 + (size_t)row * C))[lane];
        float a[4] = {av.x, av.y, av.z, av.w};
        float b[4] = {bv.x, bv.y, bv.z, bv.w};

        float m1 = a[0], m2 = b[0];
        int   i1 = 0,   i2 = 0;
#pragma unroll
        for (int j = 1; j < 4; j++) {
            if (a[j] > m1) { m1 = a[j]; i1 = j; }
            if (b[j] > m2) { m2 = b[j]; i2 = j; }
        }
        i1 += lane * 4; i2 += lane * 4;

#pragma unroll
        for (int off = 16; off; off >>= 1) {
            float om = __shfl_xor_sync(FULL, m1, off);
            int   oi = __shfl_xor_sync(FULL, i1, off);
            if (om > m1 || (om == m1 && oi < i1)) { m1 = om; i1 = oi; }
            float pm = __shfl_xor_sync(FULL, m2, off);
            int   pi = __shfl_xor_sync(FULL, i2, off);
            if (pm > m2 || (pm == m2 && pi < i2)) { m2 = pm; i2 = pi; }
        }

        float s1 = 0.f, s2 = 0.f, w1 = 0.f, w2 = 0.f;
#pragma unroll
        for (int j = 0; j < 4; j++) {
            float d  = a[j] - b[j];
            float e1 = __expf(a[j] - m1);
            float e2 = __expf(b[j] - m2);
            s1 += e1; s2 += e2;
            w1 += e1 * d; w2 -= e2 * d;
        }
#pragma unroll
        for (int off = 16; off; off >>= 1) {
            s1 += __shfl_xor_sync(FULL, s1, off);
            s2 += __shfl_xor_sync(FULL, s2, off);
            w1 += __shfl_xor_sync(FULL, w1, off);
            w2 += __shfl_xor_sync(FULL, w2, off);
        }

        int t;
        if (g_t64) t = (int)(((const long long*)targ)[row]);
        else       t = ((const int*)targ)[row];
        int ts = t & 3, tl = t >> 2;
        float ca  = (ts == 0) ? a[0] : (ts == 1) ? a[1] : (ts == 2) ? a[2] : a[3];
        float cb  = (ts == 0) ? b[0] : (ts == 1) ? b[1] : (ts == 2) ? b[2] : b[3];
        float y1t = __shfl_sync(FULL, ca, tl);
        float y2t = __shfl_sync(FULL, cb, tl);

        int ps = i1 & 3, pl = i1 >> 2;
        float cbp = (ps == 0) ? b[0] : (ps == 1) ? b[1] : (ps == 2) ? b[2] : b[3];
        float y2p = __shfl_sync(FULL, cbp, pl);

        float ls1 = __logf(s1), ls2 = __logf(s2);
        float lse1 = m1 + ls1, lse2 = m2 + ls2;

        float loss = (lse1 - y1t) + (lse2 - y2t);
        lossd = (double)loss;
        kl_i  = (double)(w1 / s1) + (double)(w2 / s2);

        float pc   = 1.0f / (s1 * s2);
        float corr = -1.0f;
        if (i1 == i2 && pc > 0.5f)
            corr = sqrtf(pc) * (ls1 + (lse2 - y2p));

        if (lane == 0) {
            g_loss[row] = loss;
            g_corr[row] = corr;
            atomicAdd(&g_h1[orderf(loss) >> 21], 1u);   // fused hist1
        }
    }

    int wid = threadIdx.x >> 5;
    if (lane == 0) { skl[wid] = kl_i; sls[wid] = lossd; }
    __syncthreads();
    if (threadIdx.x == 0) {
        double ak = 0.0, al = 0.0;
#pragma unroll
        for (int w = 0; w < 8; w++) { ak += skl[w]; al += sls[w]; }
        int slot = blockIdx.x & 31;
        atomicAdd(&g_kl_part[slot], ak);
        atomicAdd(&g_loss_part[slot], al);
    }

    // last block performs scan1 (256 threads, parallel)
    if (last_block(&g_tick1)) {
        int epoch = *((const int*)ep);
        int k = num_remember_dev(epoch, n);
        if (k < 1) k = 1;
        g_krem = 1; g_b1 = 2047u;          // fallback
        __syncthreads();
        find_bucket<2048>(g_h1, k, &g_b1, &g_krem);
    }
}

// ---------------- hist2 + (last block) scan2 --------------------------------
__global__ __launch_bounds__(256) void k_hist2(int n) {
    __shared__ unsigned sh[2048];
    for (int i = threadIdx.x; i < 2048; i += blockDim.x) sh[i] = 0;
    __syncthreads();
    unsigned b1 = g_b1;
    int stride = blockDim.x * gridDim.x;
    for (int i = blockIdx.x * blockDim.x + threadIdx.x; i < n; i += stride) {
        unsigned u = orderf(g_loss[i]);
        if ((u >> 21) == b1) atomicAdd(&sh[(u >> 10) & 2047u], 1u);
    }
    __syncthreads();
    for (int i = threadIdx.x; i < 2048; i += blockDim.x)
        if (sh[i]) atomicAdd(&g_h2[i], sh[i]);

    if (last_block(&g_tick2)) {
        int k = g_krem;
        __shared__ unsigned sb; __shared__ int skr;
        if (threadIdx.x == 0) { sb = 2047u; skr = 1; }
        __syncthreads();
        find_bucket<2048>(g_h2, k, &sb, &skr);
        __syncthreads();
        if (threadIdx.x == 0) {
            g_b12 = (g_b1 << 11) | sb;
            g_krem = skr;
        }
    }
}

// ---------------- hist3 + (last block) scan3 --------------------------------
__global__ __launch_bounds__(256) void k_hist3(int n) {
    __shared__ unsigned sh[1024];
    for (int i = threadIdx.x; i < 1024; i += blockDim.x) sh[i] = 0;
    __syncthreads();
    unsigned b12 = g_b12;
    int stride = blockDim.x * gridDim.x;
    for (int i = blockIdx.x * blockDim.x + threadIdx.x; i < n; i += stride) {
        unsigned u = orderf(g_loss[i]);
        if ((u >> 10) == b12) atomicAdd(&sh[u & 1023u], 1u);
    }
    __syncthreads();
    for (int i = threadIdx.x; i < 1024; i += blockDim.x)
        if (sh[i]) atomicAdd(&g_h3[i], sh[i]);

    if (last_block(&g_tick3)) {
        int k = g_krem;
        __shared__ unsigned sb;
        if (threadIdx.x == 0) sb = 1023u;
        __syncthreads();
        int dummy;
        find_bucket<1024>(g_h3, k, &sb, &dummy);
        __syncthreads();
        if (threadIdx.x == 0) g_key = (g_b12 << 10) | sb;
    }
}

// ---------------- reduce + (last block) finalize ----------------------------
__global__ __launch_bounds__(256) void k_reduce(const void* __restrict__ ep,
                                                int n, float* __restrict__ out) {
    unsigned key = g_key;
    double cs = 0.0, crs = 0.0;
    unsigned long long cnt = 0ull;
    int stride = blockDim.x * gridDim.x;
    for (int i = blockIdx.x * blockDim.x + threadIdx.x; i < n; i += stride) {
        float L = g_loss[i];
        unsigned u = orderf(L);
        if (u <= key) {
            cs += (double)L;
        } else {
            float c = g_corr[i];
            if (c >= 0.0f) { crs += (double)c; cnt++; }
        }
    }
#pragma unroll
    for (int off = 16; off; off >>= 1) {
        cs  += __shfl_xor_sync(FULL, cs, off);
        crs += __shfl_xor_sync(FULL, crs, off);
        cnt += __shfl_xor_sync(FULL, cnt, off);
    }
    __shared__ double sc[8], sr[8];
    __shared__ unsigned long long sn[8];
    int lane = threadIdx.x & 31, wid = threadIdx.x >> 5;
    if (lane == 0) { sc[wid] = cs; sr[wid] = crs; sn[wid] = cnt; }
    __syncthreads();
    if (threadIdx.x == 0) {
        double a = 0.0, b = 0.0; unsigned long long c = 0ull;
#pragma unroll
        for (int w = 0; w < 8; w++) { a += sc[w]; b += sr[w]; c += sn[w]; }
        atomicAdd(&g_clean_sum, a);
        atomicAdd(&g_corr_sum, b);
        atomicAdd(&g_cnt, c);
    }

    if (last_block(&g_tick4)) {
        if (threadIdx.x == 0) {
            int epoch = *((const int*)ep);
            double klsum = 0.0, lsum = 0.0;
            for (int i = 0; i < 32; i++) { klsum += g_kl_part[i]; lsum += g_loss_part[i]; }
            double res;
            if (epoch == 0) {
                res = lsum / (double)n;
            } else {
                int k = num_remember_dev(epoch, n);
                if (k < 1) k = 1;
                double clean = g_clean_sum / (double)k;
                double corrm = (g_cnt > 0ull) ? (g_corr_sum / (double)g_cnt) : 0.0;
                res = clean + corrm + 0.1 * (klsum / (double)n);
            }
            *out = (float)res;
        }
    }
}

// ---------------- launch ------------------------------------------------------
extern "C" void kernel_launch(void* const* d_in, const int* in_sizes, int n_in,
                              void* d_out, int out_size) {
    const float* y1   = (const float*)d_in[0];
    const float* y2   = (const float*)d_in[1];
    const void*  targ = d_in[2];
    const void*  ep   = d_in[3];
    int n = in_sizes[0] / C;

    k_init<<<1, 1024>>>(targ, n);
    k_main<<<(n + 7) / 8, 256>>>(y1, y2, targ, ep, n);
    k_hist2<<<256, 256>>>(n);
    k_hist3<<<256, 256>>>(n);
    k_reduce<<<256, 256>>>(ep, n, (float*)d_out);
}

// round 15
// speedup vs baseline: 1.3176x; 1.3176x over previous
#include <cuda_runtime.h>

#define FULL 0xffffffffu

constexpr int C    = 128;
constexpr int NMAX = 262144;

// ---------------- device scratch (static: no allocation allowed) ------------
__device__ float    g_loss[NMAX];
__device__ float    g_corr[NMAX];          // corr value if masked, -1.0f sentinel otherwise
__device__ unsigned g_cand[NMAX];          // compacted orderf keys matching prefix b1
__device__ double   g_kl_part[32];
__device__ double   g_loss_part[32];
__device__ double   g_clean_sum;
__device__ double   g_corr_sum;
__device__ unsigned long long g_cnt;
__device__ unsigned g_h1[2048];
__device__ unsigned g_b1, g_key, g_ccnt;
__device__ int      g_krem;
__device__ int      g_t64;
__device__ unsigned g_tick1, g_tick2, g_tick3;

// float -> order-preserving uint
__device__ __forceinline__ unsigned orderf(float f) {
    unsigned u = __float_as_uint(f);
    return (u & 0x80000000u) ? ~u : (u | 0x80000000u);
}
__device__ __forceinline__ float inv_orderf(unsigned u) {
    return __uint_as_float((u & 0x80000000u) ? (u & 0x7fffffffu) : ~u);
}

__device__ __forceinline__ int num_remember_dev(int epoch, int n) {
    double fr = fmin(0.5, (0.5 / 100.0) * (double)epoch);
    double rr = fmax(0.5, 1.0 - fr);
    return (int)(rr * (double)n);
}

// parallel "find bucket where cumsum crosses k" — 256 threads, NB buckets.
template <int NB>
__device__ __forceinline__ void find_bucket(const unsigned* hist, int k,
                                            unsigned* out_b, int* out_krem) {
    __shared__ unsigned csum[256];
    constexpr int PER = NB / 256;
    int t = threadIdx.x;
    unsigned loc[PER];
    unsigned s = 0;
#pragma unroll
    for (int j = 0; j < PER; j++) { loc[j] = hist[t * PER + j]; s += loc[j]; }
    csum[t] = s;
    __syncthreads();
#pragma unroll
    for (int off = 1; off < 256; off <<= 1) {
        unsigned v = (t >= off) ? csum[t - off] : 0u;
        __syncthreads();
        csum[t] += v;
        __syncthreads();
    }
    unsigned prev = (t == 0) ? 0u : csum[t - 1];
    if (prev < (unsigned)k && csum[t] >= (unsigned)k) {
        unsigned cum = prev;
#pragma unroll
        for (int j = 0; j < PER; j++) {
            unsigned c = loc[j];
            if (cum + c >= (unsigned)k) { *out_b = (unsigned)(t * PER + j); *out_krem = k - (int)cum; break; }
            cum += c;
        }
    }
}

__device__ __forceinline__ bool last_block(unsigned* tick) {
    __threadfence();
    __shared__ bool isLast;
    if (threadIdx.x == 0) isLast = (atomicAdd(tick, 1u) == gridDim.x - 1);
    __syncthreads();
    return isLast;
}

// ---------------- K0: init + parallel int64 detection -----------------------
__global__ void k_init(const void* __restrict__ targ, int n) {
    int t = threadIdx.x;
    for (int i = t; i < 2048; i += 1024) g_h1[i] = 0;
    if (t < 32) { g_kl_part[t] = 0.0; g_loss_part[t] = 0.0; }
    // parallel int64 detection: first warp, each lane checks one odd word
    if (t < 32) {
        const int* w = (const int*)targ;
        int nchk = (n >= 64) ? 32 : (n / 2);
        bool odd_zero = (t < nchk) ? (w[2 * t + 1] == 0) : true;
        unsigned bal = __ballot_sync(FULL, odd_zero);
        if (t == 0) g_t64 = (nchk > 0 && bal == FULL) ? 1 : 0;
    }
    if (t == 0) {
        g_clean_sum = 0.0; g_corr_sum = 0.0; g_cnt = 0ull;
        g_b1 = 2047u; g_key = 0; g_krem = 1; g_ccnt = 0u;
        g_tick1 = 0; g_tick2 = 0; g_tick3 = 0;
    }
}

// ---------------- K1: fused per-row stats, 2 rows per warp ------------------
__global__ __launch_bounds__(256) void k_main(const float* __restrict__ y1,
                                              const float* __restrict__ y2,
                                              const void*  __restrict__ targ,
                                              int n) {
    int wid  = threadIdx.x >> 5;
    int lane = threadIdx.x & 31;
    __shared__ double skl[8], sls[8];

    int rows[2] = { blockIdx.x * 16 + wid, blockIdx.x * 16 + 8 + wid };
    bool t64 = (g_t64 != 0);

    double kl_acc = 0.0, loss_acc = 0.0;

    float a[2][4], b[2][4];
    bool ok[2];
#pragma unroll
    for (int r = 0; r < 2; r++) {
        ok[r] = rows[r] < n;
        if (ok[r]) {
            const float4 av = ((const float4*)(y1 + (size_t)rows[r] * C))[lane];
            const float4 bv = ((const float4*)(y2 + (size_t)rows[r] * C))[lane];
            a[r][0] = av.x; a[r][1] = av.y; a[r][2] = av.z; a[r][3] = av.w;
            b[r][0] = bv.x; b[r][1] = bv.y; b[r][2] = bv.z; b[r][3] = bv.w;
        } else {
#pragma unroll
            for (int j = 0; j < 4; j++) { a[r][j] = 0.f; b[r][j] = 0.f; }
        }
    }

    float m1[2], m2[2];
    int   i1[2], i2[2];
#pragma unroll
    for (int r = 0; r < 2; r++) {
        // per-lane max
        float la = a[r][0], lb = b[r][0];
#pragma unroll
        for (int j = 1; j < 4; j++) {
            la = fmaxf(la, a[r][j]);
            lb = fmaxf(lb, b[r][j]);
        }
        // warp max via redux on order-preserving uints (exact)
        unsigned mo1 = __reduce_max_sync(FULL, orderf(la));
        unsigned mo2 = __reduce_max_sync(FULL, orderf(lb));
        m1[r] = inv_orderf(mo1);
        m2[r] = inv_orderf(mo2);
        // first-occurrence argmax: smallest global index with bit-equal max
        unsigned id1 = 0x7fffffffu, id2 = 0x7fffffffu;
#pragma unroll
        for (int j = 3; j >= 0; j--) {
            if (orderf(a[r][j]) == mo1) id1 = (unsigned)(lane * 4 + j);
            if (orderf(b[r][j]) == mo2) id2 = (unsigned)(lane * 4 + j);
        }
        i1[r] = (int)__reduce_min_sync(FULL, id1);
        i2[r] = (int)__reduce_min_sync(FULL, id2);
    }

    float s1[2], s2[2], w1[2], w2[2];
#pragma unroll
    for (int r = 0; r < 2; r++) {
        float ps1 = 0.f, ps2 = 0.f, pw1 = 0.f, pw2 = 0.f;
#pragma unroll
        for (int j = 0; j < 4; j++) {
            float d  = a[r][j] - b[r][j];
            float e1 = __expf(a[r][j] - m1[r]);
            float e2 = __expf(b[r][j] - m2[r]);
            ps1 += e1; ps2 += e2;
            pw1 += e1 * d; pw2 -= e2 * d;
        }
        s1[r] = ps1; s2[r] = ps2; w1[r] = pw1; w2[r] = pw2;
    }
    // butterfly sums, both rows interleaved for ILP
#pragma unroll
    for (int off = 16; off; off >>= 1) {
#pragma unroll
        for (int r = 0; r < 2; r++) {
            s1[r] += __shfl_xor_sync(FULL, s1[r], off);
            s2[r] += __shfl_xor_sync(FULL, s2[r], off);
            w1[r] += __shfl_xor_sync(FULL, w1[r], off);
            w2[r] += __shfl_xor_sync(FULL, w2[r], off);
        }
    }

#pragma unroll
    for (int r = 0; r < 2; r++) {
        if (!ok[r]) continue;
        int t;
        if (t64) t = (int)(((const long long*)targ)[rows[r]]);
        else     t = ((const int*)targ)[rows[r]];
        int ts = t & 3, tl = t >> 2;
        float ca  = (ts == 0) ? a[r][0] : (ts == 1) ? a[r][1] : (ts == 2) ? a[r][2] : a[r][3];
        float cb  = (ts == 0) ? b[r][0] : (ts == 1) ? b[r][1] : (ts == 2) ? b[r][2] : b[r][3];
        float y1t = __shfl_sync(FULL, ca, tl);
        float y2t = __shfl_sync(FULL, cb, tl);

        int ps = i1[r] & 3, pl = i1[r] >> 2;
        float cbp = (ps == 0) ? b[r][0] : (ps == 1) ? b[r][1] : (ps == 2) ? b[r][2] : b[r][3];
        float y2p = __shfl_sync(FULL, cbp, pl);

        float ls1 = __logf(s1[r]), ls2 = __logf(s2[r]);
        float lse1 = m1[r] + ls1, lse2 = m2[r] + ls2;

        float loss = (lse1 - y1t) + (lse2 - y2t);
        loss_acc += (double)loss;
        kl_acc   += (double)(w1[r] / s1[r]) + (double)(w2[r] / s2[r]);

        float pc   = 1.0f / (s1[r] * s2[r]);
        float corr = -1.0f;
        if (i1[r] == i2[r] && pc > 0.5f)
            corr = sqrtf(pc) * (ls1 + (lse2 - y2p));

        if (lane == 0) {
            g_loss[rows[r]] = loss;
            g_corr[rows[r]] = corr;
        }
    }

    if (lane == 0) { skl[wid] = kl_acc; sls[wid] = loss_acc; }
    __syncthreads();
    if (threadIdx.x == 0) {
        double ak = 0.0, al = 0.0;
#pragma unroll
        for (int w = 0; w < 8; w++) { ak += skl[w]; al += sls[w]; }
        int slot = blockIdx.x & 31;
        atomicAdd(&g_kl_part[slot], ak);
        atomicAdd(&g_loss_part[slot], al);
    }
}

// ---------------- K2: hist1 (shared-aggregated) + scan1 in last block -------
__global__ __launch_bounds__(256) void k_hist1(const void* __restrict__ ep, int n) {
    __shared__ unsigned sh[2048];
    for (int i = threadIdx.x; i < 2048; i += blockDim.x) sh[i] = 0;
    __syncthreads();
    int stride = blockDim.x * gridDim.x;
    for (int i = blockIdx.x * blockDim.x + threadIdx.x; i < n; i += stride)
        atomicAdd(&sh[orderf(g_loss[i]) >> 21], 1u);
    __syncthreads();
    for (int i = threadIdx.x; i < 2048; i += blockDim.x)
        if (sh[i]) atomicAdd(&g_h1[i], sh[i]);

    if (last_block(&g_tick1)) {
        int epoch = *((const int*)ep);
        int k = num_remember_dev(epoch, n);
        if (k < 1) k = 1;
        find_bucket<2048>(g_h1, k, &g_b1, &g_krem);   // defaults set in k_init
    }
}

// ---------------- K3: compact candidates + last-block exact select ----------
__global__ __launch_bounds__(256) void k_sel(int n) {
    unsigned b1 = g_b1;
    int lane = threadIdx.x & 31;
    int stride = blockDim.x * gridDim.x;
    for (int i = blockIdx.x * blockDim.x + threadIdx.x; i < n; i += stride) {
        unsigned u = orderf(g_loss[i]);
        bool m = (u >> 21) == b1;
        unsigned mask = __ballot_sync(FULL, m);
        if (mask) {
            int leader = __ffs(mask) - 1;
            unsigned base = 0;
            if (lane == leader) base = atomicAdd(&g_ccnt, (unsigned)__popc(mask));
            base = __shfl_sync(FULL, base, leader);
            if (m) {
                int rank = __popc(mask & ((1u << lane) - 1));
                g_cand[base + rank] = u;
            }
        }
    }

    if (last_block(&g_tick2)) {
        __shared__ unsigned sh[2048];
        __shared__ unsigned sb2, sb3;
        __shared__ int skr2;
        int t = threadIdx.x;
        for (int i = t; i < 2048; i += 256) sh[i] = 0;
        if (t == 0) { sb2 = 2047u; skr2 = 1; sb3 = 1023u; }
        __syncthreads();
        unsigned M = g_ccnt;
        int k = g_krem;
        for (unsigned i = t; i < M; i += 256)
            atomicAdd(&sh[(g_cand[i] >> 10) & 2047u], 1u);
        __syncthreads();
        find_bucket<2048>(sh, k, &sb2, &skr2);
        __syncthreads();
        unsigned b2 = sb2; int k2 = skr2;
        for (int i = t; i < 1024; i += 256) sh[i] = 0;
        __syncthreads();
        for (unsigned i = t; i < M; i += 256) {
            unsigned u = g_cand[i];
            if (((u >> 10) & 2047u) == b2) atomicAdd(&sh[u & 1023u], 1u);
        }
        __syncthreads();
        int dummy;
        find_bucket<1024>(sh, k2, &sb3, &dummy);
        __syncthreads();
        if (t == 0) g_key = (b1 << 21) | (b2 << 10) | sb3;
    }
}

// ---------------- K4: reduce + (last block) finalize ------------------------
__global__ __launch_bounds__(256) void k_reduce(const void* __restrict__ ep,
                                                int n, float* __restrict__ out) {
    unsigned key = g_key;
    double cs = 0.0, crs = 0.0;
    unsigned long long cnt = 0ull;
    int stride = blockDim.x * gridDim.x;
    for (int i = blockIdx.x * blockDim.x + threadIdx.x; i < n; i += stride) {
        float L = g_loss[i];
        unsigned u = orderf(L);
        if (u <= key) {
            cs += (double)L;
        } else {
            float c = g_corr[i];
            if (c >= 0.0f) { crs += (double)c; cnt++; }
        }
    }
#pragma unroll
    for (int off = 16; off; off >>= 1) {
        cs  += __shfl_xor_sync(FULL, cs, off);
        crs += __shfl_xor_sync(FULL, crs, off);
        cnt += __shfl_xor_sync(FULL, cnt, off);
    }
    __shared__ double sc[8], sr[8];
    __shared__ unsigned long long sn[8];
    int lane = threadIdx.x & 31, wid = threadIdx.x >> 5;
    if (lane == 0) { sc[wid] = cs; sr[wid] = crs; sn[wid] = cnt; }
    __syncthreads();
    if (threadIdx.x == 0) {
        double a = 0.0, b = 0.0; unsigned long long c = 0ull;
#pragma unroll
        for (int w = 0; w < 8; w++) { a += sc[w]; b += sr[w]; c += sn[w]; }
        atomicAdd(&g_clean_sum, a);
        atomicAdd(&g_corr_sum, b);
        atomicAdd(&g_cnt, c);
    }

    if (last_block(&g_tick3)) {
        if (threadIdx.x == 0) {
            int epoch = *((const int*)ep);
            double klsum = 0.0, lsum = 0.0;
            for (int i = 0; i < 32; i++) { klsum += g_kl_part[i]; lsum += g_loss_part[i]; }
            double res;
            if (epoch == 0) {
                res = lsum / (double)n;
            } else {
                int k = num_remember_dev(epoch, n);
                if (k < 1) k = 1;
                double clean = g_clean_sum / (double)k;
                double corrm = (g_cnt > 0ull) ? (g_corr_sum / (double)g_cnt) : 0.0;
                res = clean + corrm + 0.1 * (klsum / (double)n);
            }
            *out = (float)res;
        }
    }
}

// ---------------- launch ------------------------------------------------------
extern "C" void kernel_launch(void* const* d_in, const int* in_sizes, int n_in,
                              void* d_out, int out_size) {
    const float* y1   = (const float*)d_in[0];
    const float* y2   = (const float*)d_in[1];
    const void*  targ = d_in[2];
    const void*  ep   = d_in[3];
    int n = in_sizes[0] / C;

    k_init<<<1, 1024>>>(targ, n);
    k_main<<<(n + 15) / 16, 256>>>(y1, y2, targ, n);
    k_hist1<<<512, 256>>>(ep, n);
    k_sel<<<512, 256>>>(n);
    k_reduce<<<512, 256>>>(ep, n, (float*)d_out);
}

// round 16
// speedup vs baseline: 1.3810x; 1.0481x over previous
#include <cuda_runtime.h>

#define FULL 0xffffffffu

constexpr int C    = 128;
constexpr int NMAX = 262144;
constexpr int NB1  = 4096;   // 12-bit level 1
constexpr int NB2  = 1024;   // 10-bit level 2
constexpr int NB3  = 1024;   // 10-bit level 3
constexpr int MAXB = 1024;   // max persistent blocks

// ---------------- device scratch (static: no allocation allowed) ------------
__device__ float    g_loss[NMAX];
__device__ float    g_corr[NMAX];          // corr value if masked, -1.0f sentinel
__device__ double   g_kl_blk[MAXB], g_ls_blk[MAXB];
__device__ double   g_clean_sum, g_corr_sum;
__device__ unsigned long long g_cnt;
__device__ unsigned g_h1[NB1], g_h2[NB2], g_h3[NB3];
__device__ unsigned g_sync[8];
__device__ int      g_t64;

// float -> order-preserving uint
__device__ __forceinline__ unsigned orderf(float f) {
    unsigned u = __float_as_uint(f);
    return (u & 0x80000000u) ? ~u : (u | 0x80000000u);
}
__device__ __forceinline__ float inv_orderf(unsigned u) {
    return __uint_as_float((u & 0x80000000u) ? (u & 0x7fffffffu) : ~u);
}

__device__ __forceinline__ int num_remember_dev(int epoch, int n) {
    double fr = fmin(0.5, (0.5 / 100.0) * (double)epoch);
    double rr = fmax(0.5, 1.0 - fr);
    return (int)(rr * (double)n);
}

// software grid barrier: all blocks co-resident (grid sized via occupancy API)
__device__ __forceinline__ void gsync(int idx, unsigned nb) {
    __syncthreads();
    if (threadIdx.x == 0) {
        __threadfence();
        unsigned arr = atomicAdd(&g_sync[idx], 1u) + 1u;
        if (arr < nb) {
            while (*(volatile unsigned*)&g_sync[idx] < nb) { }
        }
        __threadfence();
    }
    __syncthreads();
}

// parallel "find bucket where cumsum crosses k"; every thread gets (b, krem).
template <int NB>
__device__ __forceinline__ void find_bucket_g(const unsigned* __restrict__ hist, int k,
                                              unsigned* csum,           // smem[256]
                                              volatile unsigned* s_b,   // smem scalar
                                              volatile int* s_k,        // smem scalar
                                              unsigned& b_out, int& k_out) {
    constexpr int PER = NB / 256;
    int t = threadIdx.x;
    if (t == 0) { *s_b = NB - 1; *s_k = 1; }
    unsigned loc[PER];
    unsigned s = 0;
#pragma unroll
    for (int j = 0; j < PER; j++) { loc[j] = __ldcg(&hist[t * PER + j]); s += loc[j]; }
    csum[t] = s;
    __syncthreads();
#pragma unroll
    for (int off = 1; off < 256; off <<= 1) {
        unsigned v = (t >= off) ? csum[t - off] : 0u;
        __syncthreads();
        csum[t] += v;
        __syncthreads();
    }
    unsigned prev = (t == 0) ? 0u : csum[t - 1];
    if (prev < (unsigned)k && csum[t] >= (unsigned)k) {
        unsigned cum = prev;
#pragma unroll
        for (int j = 0; j < PER; j++) {
            unsigned c = loc[j];
            if (cum + c >= (unsigned)k) { *s_b = (unsigned)(t * PER + j); *s_k = k - (int)cum; break; }
            cum += c;
        }
    }
    __syncthreads();
    b_out = *s_b;
    k_out = *s_k;
    __syncthreads();
}

// ---------------- K0: init + parallel int64 detection -----------------------
__global__ void k_init(const void* __restrict__ targ, int n) {
    int t = threadIdx.x;
    for (int i = t; i < NB1; i += 1024) g_h1[i] = 0;
    for (int i = t; i < NB2; i += 1024) g_h2[i] = 0;
    for (int i = t; i < NB3; i += 1024) g_h3[i] = 0;
    if (t < 8) g_sync[t] = 0;
    if (t < 32) {
        const int* w = (const int*)targ;
        int nchk = (n >= 64) ? 32 : (n / 2);
        bool odd_zero = (t < nchk) ? (w[2 * t + 1] == 0) : true;
        unsigned bal = __ballot_sync(FULL, odd_zero);
        if (t == 0) g_t64 = (nchk > 0 && bal == FULL) ? 1 : 0;
    }
    if (t == 0) { g_clean_sum = 0.0; g_corr_sum = 0.0; g_cnt = 0ull; }
}

// ---------------- fused persistent kernel -----------------------------------
__global__ __launch_bounds__(256) void k_fused(const float* __restrict__ y1,
                                               const float* __restrict__ y2,
                                               const void*  __restrict__ targ,
                                               const void*  __restrict__ ep,
                                               int n, float* __restrict__ out) {
    __shared__ unsigned sh[NB1];          // 16 KB: hist L1, reused for L2/L3
    __shared__ unsigned csum[256];
    __shared__ double   skl[8], sls[8];
    __shared__ double   dred[256];
    __shared__ unsigned s_b; __shared__ int s_k;

    const int tid  = threadIdx.x;
    const int lane = tid & 31;
    const int wid  = tid >> 5;
    const unsigned nb = gridDim.x;
    const bool t64 = (g_t64 != 0);

    for (int i = tid; i < NB1; i += 256) sh[i] = 0;
    __syncthreads();

    // ---------------- phase 1: per-row stats + 12-bit smem hist -------------
    double kl_acc = 0.0, ls_acc = 0.0;
    const int gw = blockIdx.x * 8 + wid;        // global warp id
    const int GW = (int)nb * 8;

    for (int base = gw * 2; base < n; base += GW * 2) {
        int rows[2] = { base, base + 1 };
        float a[2][4], b[2][4];
        bool ok[2];
#pragma unroll
        for (int r = 0; r < 2; r++) {
            ok[r] = rows[r] < n;
            if (ok[r]) {
                const float4 av = ((const float4*)(y1 + (size_t)rows[r] * C))[lane];
                const float4 bv = ((const float4*)(y2 + (size_t)rows[r] * C))[lane];
                a[r][0] = av.x; a[r][1] = av.y; a[r][2] = av.z; a[r][3] = av.w;
                b[r][0] = bv.x; b[r][1] = bv.y; b[r][2] = bv.z; b[r][3] = bv.w;
            } else {
#pragma unroll
                for (int j = 0; j < 4; j++) { a[r][j] = 0.f; b[r][j] = 0.f; }
            }
        }

        float m1[2], m2[2]; int i1[2], i2[2];
#pragma unroll
        for (int r = 0; r < 2; r++) {
            float la = fmaxf(fmaxf(a[r][0], a[r][1]), fmaxf(a[r][2], a[r][3]));
            float lb = fmaxf(fmaxf(b[r][0], b[r][1]), fmaxf(b[r][2], b[r][3]));
            unsigned mo1 = __reduce_max_sync(FULL, orderf(la));
            unsigned mo2 = __reduce_max_sync(FULL, orderf(lb));
            m1[r] = inv_orderf(mo1);
            m2[r] = inv_orderf(mo2);
            unsigned id1 = 0x7fffffffu, id2 = 0x7fffffffu;
#pragma unroll
            for (int j = 3; j >= 0; j--) {
                if (orderf(a[r][j]) == mo1) id1 = (unsigned)(lane * 4 + j);
                if (orderf(b[r][j]) == mo2) id2 = (unsigned)(lane * 4 + j);
            }
            i1[r] = (int)__reduce_min_sync(FULL, id1);
            i2[r] = (int)__reduce_min_sync(FULL, id2);
        }

        float s1[2], s2[2], w1[2], w2[2];
#pragma unroll
        for (int r = 0; r < 2; r++) {
            float ps1 = 0.f, ps2 = 0.f, pw1 = 0.f, pw2 = 0.f;
#pragma unroll
            for (int j = 0; j < 4; j++) {
                float d  = a[r][j] - b[r][j];
                float e1 = __expf(a[r][j] - m1[r]);
                float e2 = __expf(b[r][j] - m2[r]);
                ps1 += e1; ps2 += e2;
                pw1 += e1 * d; pw2 -= e2 * d;
            }
            s1[r] = ps1; s2[r] = ps2; w1[r] = pw1; w2[r] = pw2;
        }
#pragma unroll
        for (int off = 16; off; off >>= 1) {
#pragma unroll
            for (int r = 0; r < 2; r++) {
                s1[r] += __shfl_xor_sync(FULL, s1[r], off);
                s2[r] += __shfl_xor_sync(FULL, s2[r], off);
                w1[r] += __shfl_xor_sync(FULL, w1[r], off);
                w2[r] += __shfl_xor_sync(FULL, w2[r], off);
            }
        }

#pragma unroll
        for (int r = 0; r < 2; r++) {
            if (!ok[r]) continue;
            int t;
            if (t64) t = (int)(((const long long*)targ)[rows[r]]);
            else     t = ((const int*)targ)[rows[r]];
            int ts = t & 3, tl = t >> 2;
            float ca  = (ts == 0) ? a[r][0] : (ts == 1) ? a[r][1] : (ts == 2) ? a[r][2] : a[r][3];
            float cb  = (ts == 0) ? b[r][0] : (ts == 1) ? b[r][1] : (ts == 2) ? b[r][2] : b[r][3];
            float y1t = __shfl_sync(FULL, ca, tl);
            float y2t = __shfl_sync(FULL, cb, tl);

            int ps = i1[r] & 3, pl = i1[r] >> 2;
            float cbp = (ps == 0) ? b[r][0] : (ps == 1) ? b[r][1] : (ps == 2) ? b[r][2] : b[r][3];
            float y2p = __shfl_sync(FULL, cbp, pl);

            float ls1 = __logf(s1[r]), ls2 = __logf(s2[r]);
            float lse1 = m1[r] + ls1, lse2 = m2[r] + ls2;

            float loss = (lse1 - y1t) + (lse2 - y2t);

            float pc   = 1.0f / (s1[r] * s2[r]);
            float corr = -1.0f;
            if (i1[r] == i2[r] && pc > 0.5f)
                corr = sqrtf(pc) * (ls1 + (lse2 - y2p));

            if (lane == 0) {
                ls_acc += (double)loss;
                kl_acc += (double)(w1[r] / s1[r]) + (double)(w2[r] / s2[r]);
                g_loss[rows[r]] = loss;
                g_corr[rows[r]] = corr;
                atomicAdd(&sh[orderf(loss) >> 20], 1u);
            }
        }
    }

    if (lane == 0) { skl[wid] = kl_acc; sls[wid] = ls_acc; }
    __syncthreads();
    if (tid == 0) {
        double ak = 0.0, al = 0.0;
#pragma unroll
        for (int w = 0; w < 8; w++) { ak += skl[w]; al += sls[w]; }
        g_kl_blk[blockIdx.x] = ak;
        g_ls_blk[blockIdx.x] = al;
    }
    __syncthreads();
    for (int i = tid; i < NB1; i += 256) {
        unsigned v = sh[i];
        if (v) atomicAdd(&g_h1[i], v);
    }

    gsync(0, nb);

    // ---------------- select: scan1 (all blocks, redundant) -----------------
    const int epoch = *((const int*)ep);
    int k = num_remember_dev(epoch, n);
    if (k < 1) k = 1;
    unsigned b1; int k1;
    find_bucket_g<NB1>(g_h1, k, csum, &s_b, &s_k, b1, k1);

    // ---------------- hist L2 over L2-resident loss array -------------------
    for (int i = tid; i < NB2; i += 256) sh[i] = 0;
    __syncthreads();
    {
        int stride = (int)nb * 256;
        for (int i = blockIdx.x * 256 + tid; i < n; i += stride) {
            unsigned u = orderf(g_loss[i]);
            if ((u >> 20) == b1) atomicAdd(&sh[(u >> 10) & 1023u], 1u);
        }
    }
    __syncthreads();
    for (int i = tid; i < NB2; i += 256) {
        unsigned v = sh[i];
        if (v) atomicAdd(&g_h2[i], v);
    }
    gsync(1, nb);

    unsigned b2; int k2;
    find_bucket_g<NB2>(g_h2, k1, csum, &s_b, &s_k, b2, k2);

    // ---------------- hist L3 ------------------------------------------------
    for (int i = tid; i < NB3; i += 256) sh[i] = 0;
    __syncthreads();
    {
        unsigned pfx = (b1 << 10) | b2;
        int stride = (int)nb * 256;
        for (int i = blockIdx.x * 256 + tid; i < n; i += stride) {
            unsigned u = orderf(g_loss[i]);
            if ((u >> 10) == pfx) atomicAdd(&sh[u & 1023u], 1u);
        }
    }
    __syncthreads();
    for (int i = tid; i < NB3; i += 256) {
        unsigned v = sh[i];
        if (v) atomicAdd(&g_h3[i], v);
    }
    gsync(2, nb);

    unsigned b3; int k3;
    find_bucket_g<NB3>(g_h3, k2, csum, &s_b, &s_k, b3, k3);
    const unsigned key = (b1 << 20) | (b2 << 10) | b3;

    // ---------------- reduce: clean sum + masked correction ------------------
    {
        double cs = 0.0, crs = 0.0;
        unsigned long long cnt = 0ull;
        int stride = (int)nb * 256;
        for (int i = blockIdx.x * 256 + tid; i < n; i += stride) {
            float L = g_loss[i];
            unsigned u = orderf(L);
            if (u <= key) {
                cs += (double)L;
            } else {
                float c = g_corr[i];
                if (c >= 0.0f) { crs += (double)c; cnt++; }
            }
        }
#pragma unroll
        for (int off = 16; off; off >>= 1) {
            cs  += __shfl_xor_sync(FULL, cs, off);
            crs += __shfl_xor_sync(FULL, crs, off);
            cnt += __shfl_xor_sync(FULL, cnt, off);
        }
        if (lane == 0) { skl[wid] = cs; sls[wid] = crs; csum[wid] = (unsigned)cnt; }
        __syncthreads();
        if (tid == 0) {
            double a = 0.0, b = 0.0; unsigned long long c = 0ull;
#pragma unroll
            for (int w = 0; w < 8; w++) { a += skl[w]; b += sls[w]; c += csum[w]; }
            atomicAdd(&g_clean_sum, a);
            atomicAdd(&g_corr_sum, b);
            atomicAdd(&g_cnt, c);
        }
    }
    gsync(3, nb);

    // ---------------- finalize (block 0) -------------------------------------
    if (blockIdx.x == 0) {
        double kv = 0.0, lv = 0.0;
        for (unsigned i = tid; i < nb; i += 256) { kv += g_kl_blk[i]; lv += g_ls_blk[i]; }
        dred[tid] = kv;
        __syncthreads();
        for (int off = 128; off; off >>= 1) {
            if (tid < off) dred[tid] += dred[tid + off];
            __syncthreads();
        }
        double klsum = dred[0];
        __syncthreads();
        dred[tid] = lv;
        __syncthreads();
        for (int off = 128; off; off >>= 1) {
            if (tid < off) dred[tid] += dred[tid + off];
            __syncthreads();
        }
        double lsum = dred[0];

        if (tid == 0) {
            double res;
            if (epoch == 0) {
                res = lsum / (double)n;
            } else {
                double clean = g_clean_sum / (double)k;
                unsigned long long cc = g_cnt;
                double corrm = (cc > 0ull) ? (g_corr_sum / (double)cc) : 0.0;
                res = clean + corrm + 0.1 * (klsum / (double)n);
            }
            *out = (float)res;
        }
    }
}

// ---------------- launch ------------------------------------------------------
extern "C" void kernel_launch(void* const* d_in, const int* in_sizes, int n_in,
                              void* d_out, int out_size) {
    const float* y1   = (const float*)d_in[0];
    const float* y2   = (const float*)d_in[1];
    const void*  targ = d_in[2];
    const void*  ep   = d_in[3];
    int n = in_sizes[0] / C;

    int dev = 0;
    cudaGetDevice(&dev);
    int sms = 148;
    cudaDeviceGetAttribute(&sms, cudaDevAttrMultiProcessorCount, dev);
    int maxb = 1;
    cudaOccupancyMaxActiveBlocksPerMultiprocessor(&maxb, k_fused, 256, 0);
    if (maxb < 1) maxb = 1;
    if (maxb > 4) maxb = 4;                 // phase-1 is memory-bound; 4/SM plenty
    int nb = sms * maxb;
    if (nb > MAXB) nb = MAXB;

    k_init<<<1, 1024>>>(targ, n);
    k_fused<<<nb, 256>>>(y1, y2, targ, ep, n, (float*)d_out);
}

// round 17
// speedup vs baseline: 1.7364x; 1.2573x over previous
#include <cuda_runtime.h>

#define FULL 0xffffffffu

constexpr int C    = 128;
constexpr int NMAX = 262144;
constexpr int NB1  = 2048;   // 11-bit level 1
constexpr int NB2  = 2048;   // 11-bit level 2
constexpr int NB3  = 1024;   // 10-bit level 3
constexpr int MAXB = 1024;
constexpr int TR   = 256;    // rows per tile (= block threads)
constexpr int CH   = 8;      // cols per chunk
constexpr int NCH  = C / CH; // 16 chunks
constexpr int PITCH = 9;     // smem pitch in words (gcd(9,32)=1 -> conflict-free)

// ---------------- device scratch ---------------------------------------------
__device__ float    g_loss[NMAX];
__device__ float    g_corr[NMAX];
__device__ double   g_kl_blk[MAXB], g_ls_blk[MAXB];
__device__ double   g_clean_sum, g_corr_sum;
__device__ unsigned long long g_cnt;
__device__ unsigned g_h1[NB1], g_h2[NB2], g_h3[NB3];
__device__ unsigned g_sync[8];
__device__ int      g_t64;

__device__ __forceinline__ unsigned orderf(float f) {
    unsigned u = __float_as_uint(f);
    return (u & 0x80000000u) ? ~u : (u | 0x80000000u);
}

__device__ __forceinline__ int num_remember_dev(int epoch, int n) {
    double fr = fmin(0.5, (0.5 / 100.0) * (double)epoch);
    double rr = fmax(0.5, 1.0 - fr);
    return (int)(rr * (double)n);
}

__device__ __forceinline__ void gsync(int idx, unsigned nb) {
    __syncthreads();
    if (threadIdx.x == 0) {
        __threadfence();
        unsigned arr = atomicAdd(&g_sync[idx], 1u) + 1u;
        if (arr < nb) {
            while (*(volatile unsigned*)&g_sync[idx] < nb) { }
        }
        __threadfence();
    }
    __syncthreads();
}

// parallel "find bucket where cumsum crosses k"; every thread gets (b, krem)
template <int NB>
__device__ __forceinline__ void find_bucket_g(const unsigned* __restrict__ hist, int k,
                                              unsigned* csum,
                                              volatile unsigned* s_b, volatile int* s_k,
                                              unsigned& b_out, int& k_out) {
    constexpr int PER = NB / 256;
    int t = threadIdx.x;
    if (t == 0) { *s_b = NB - 1; *s_k = 1; }
    unsigned loc[PER];
    unsigned s = 0;
#pragma unroll
    for (int j = 0; j < PER; j++) { loc[j] = __ldcg(&hist[t * PER + j]); s += loc[j]; }
    csum[t] = s;
    __syncthreads();
#pragma unroll
    for (int off = 1; off < 256; off <<= 1) {
        unsigned v = (t >= off) ? csum[t - off] : 0u;
        __syncthreads();
        csum[t] += v;
        __syncthreads();
    }
    unsigned prev = (t == 0) ? 0u : csum[t - 1];
    if (prev < (unsigned)k && csum[t] >= (unsigned)k) {
        unsigned cum = prev;
#pragma unroll
        for (int j = 0; j < PER; j++) {
            unsigned c = loc[j];
            if (cum + c >= (unsigned)k) { *s_b = (unsigned)(t * PER + j); *s_k = k - (int)cum; break; }
            cum += c;
        }
    }
    __syncthreads();
    b_out = *s_b;
    k_out = *s_k;
    __syncthreads();
}

// ---------------- K0: init + parallel int64 detection -----------------------
__global__ void k_init(const void* __restrict__ targ, int n) {
    int t = threadIdx.x;
    for (int i = t; i < NB1; i += 1024) g_h1[i] = 0;
    for (int i = t; i < NB2; i += 1024) g_h2[i] = 0;
    for (int i = t; i < NB3; i += 1024) g_h3[i] = 0;
    if (t < 8) g_sync[t] = 0;
    if (t < 32) {
        const int* w = (const int*)targ;
        int nchk = (n >= 64) ? 32 : (n / 2);
        bool odd_zero = (t < nchk) ? (w[2 * t + 1] == 0) : true;
        unsigned bal = __ballot_sync(FULL, odd_zero);
        if (t == 0) g_t64 = (nchk > 0 && bal == FULL) ? 1 : 0;
    }
    if (t == 0) { g_clean_sum = 0.0; g_corr_sum = 0.0; g_cnt = 0ull; }
}

// ---------------- fused persistent kernel -----------------------------------
__global__ __launch_bounds__(256, 4) void k_fused(const float* __restrict__ y1,
                                                  const float* __restrict__ y2,
                                                  const void*  __restrict__ targ,
                                                  const void*  __restrict__ ep,
                                                  int n, float* __restrict__ out) {
    // 9216 (sA) + 9216 (sB) + 8192 (h1loc) = 26624 bytes
    __shared__ __align__(16) unsigned char SM[2 * TR * PITCH * 4 + NB1 * 4];
    float*    sA    = (float*)SM;                          // [TR*PITCH]
    float*    sB    = (float*)(SM + TR * PITCH * 4);       // [TR*PITCH]
    unsigned* h1loc = (unsigned*)(SM + 2 * TR * PITCH * 4);// [NB1]
    // later-phase aliases (inside sA/sB regions, used after phase 1)
    unsigned* hL   = (unsigned*)SM;                        // up to 2048 entries
    unsigned* csum = (unsigned*)(SM + 8192);               // 256 uints
    double*   dred = (double*)(SM + 10240);                // 256 doubles
    __shared__ unsigned s_b; __shared__ int s_k;
    __shared__ double skl[8], sls[8];
    __shared__ unsigned long long scnt[8];

    const int tid  = threadIdx.x;
    const int lane = tid & 31;
    const int wid  = tid >> 5;
    const unsigned nbk = gridDim.x;
    const bool t64 = (g_t64 != 0);

    for (int i = tid; i < NB1; i += 256) h1loc[i] = 0;

    // ---------------- phase 1: thread-per-row online scan -------------------
    double kl_acc = 0.0, ls_acc = 0.0;
    const int ntiles = (n + TR - 1) / TR;

    for (int tb = blockIdx.x; tb < ntiles; tb += (int)nbk) {
        const int tile0 = tb * TR;
        const int row   = tile0 + tid;
        const bool ok   = row < n;

        // staging assignment: thread stages float4s f = tid + 256*j (j=0,1)
        const float4* pa[2]; const float4* pb[2];
        int sbase_st[2];
#pragma unroll
        for (int j = 0; j < 2; j++) {
            int f = tid + 256 * j;
            int rf = f >> 1, qf = f & 1;
            int gr = tile0 + rf; if (gr >= n) gr = n - 1;
            pa[j] = (const float4*)(y1 + (size_t)gr * C) + qf;
            pb[j] = (const float4*)(y2 + (size_t)gr * C) + qf;
            sbase_st[j] = rf * PITCH + qf * 4;
        }

        float m1 = -3.4e38f, m2 = -3.4e38f;
        float s1 = 0.f, s2 = 0.f, w1 = 0.f, w2 = 0.f;
        float y1t = 0.f, y2t = 0.f, bat = 0.f;
        int i1 = 0, i2 = 0, tcol = 0;
        if (ok) tcol = t64 ? (int)(((const long long*)targ)[row])
                           : ((const int*)targ)[row];

        float4 rA[2], rB[2];
#pragma unroll
        for (int j = 0; j < 2; j++) { rA[j] = pa[j][0]; rB[j] = pb[j][0]; }

        const int sbase = tid * PITCH;
#pragma unroll 1
        for (int c = 0; c < NCH; c++) {
            __syncthreads();   // previous chunk's compute done -> safe to overwrite
#pragma unroll
            for (int j = 0; j < 2; j++) {
                int bs = sbase_st[j];
                sA[bs] = rA[j].x; sA[bs+1] = rA[j].y; sA[bs+2] = rA[j].z; sA[bs+3] = rA[j].w;
                sB[bs] = rB[j].x; sB[bs+1] = rB[j].y; sB[bs+2] = rB[j].z; sB[bs+3] = rB[j].w;
            }
            __syncthreads();   // staged data visible
            if (c + 1 < NCH) {
#pragma unroll
                for (int j = 0; j < 2; j++) {
                    rA[j] = pa[j][(c + 1) * 2];
                    rB[j] = pb[j][(c + 1) * 2];
                }
            }
            if (ok) {
                const int colbase = c * CH;
#pragma unroll
                for (int k = 0; k < CH; k++) {
                    float v1 = sA[sbase + k], v2 = sB[sbase + k];
                    float d  = v1 - v2;
                    float e1 = __expf(v1), e2 = __expf(v2);
                    s1 += e1; s2 += e2;
                    w1 = __fmaf_rn(e1, d, w1);
                    w2 = __fmaf_rn(e2, d, w2);
                    int col = colbase + k;
                    if (v1 > m1) { m1 = v1; i1 = col; bat = v2; }
                    if (v2 > m2) { m2 = v2; i2 = col; }
                    if (col == tcol) { y1t = v1; y2t = v2; }
                }
            }
        }

        if (ok) {
            float ls1 = __logf(s1), ls2 = __logf(s2);
            float loss = (ls1 - y1t) + (ls2 - y2t);
            float pc   = __expf(m1 + m2 - ls1 - ls2);   // conf1*conf2
            float corr = -1.0f;
            if (i1 == i2 && pc > 0.5f)
                corr = sqrtf(pc) * ((ls1 - m1) + (ls2 - bat));
            g_loss[row] = loss;
            g_corr[row] = corr;
            atomicAdd(&h1loc[orderf(loss) >> 21], 1u);
            ls_acc += (double)loss;
            kl_acc += (double)(w1 / s1) - (double)(w2 / s2);
        }
    }

    // block-level double reduction (dred aliases sB region — compute is done)
    __syncthreads();
    dred[tid] = kl_acc;
    __syncthreads();
    for (int off = 128; off; off >>= 1) {
        if (tid < off) dred[tid] += dred[tid + off];
        __syncthreads();
    }
    if (tid == 0) g_kl_blk[blockIdx.x] = dred[0];
    __syncthreads();
    dred[tid] = ls_acc;
    __syncthreads();
    for (int off = 128; off; off >>= 1) {
        if (tid < off) dred[tid] += dred[tid + off];
        __syncthreads();
    }
    if (tid == 0) g_ls_blk[blockIdx.x] = dred[0];
    __syncthreads();

    // flush local hist (nonzero only)
    for (int i = tid; i < NB1; i += 256) {
        unsigned v = h1loc[i];
        if (v) atomicAdd(&g_h1[i], v);
    }
    gsync(0, nbk);

    // ---------------- select level 1 ----------------------------------------
    const int epoch = *((const int*)ep);
    int kk = num_remember_dev(epoch, n);
    if (kk < 1) kk = 1;
    unsigned b1; int k1;
    find_bucket_g<NB1>(g_h1, kk, csum, &s_b, &s_k, b1, k1);

    // ---------------- level 2 hist over L2-resident loss --------------------
    for (int i = tid; i < NB2; i += 256) hL[i] = 0;
    __syncthreads();
    const int stride = (int)nbk * 256;
    for (int i = blockIdx.x * 256 + tid; i < n; i += stride) {
        unsigned u = orderf(g_loss[i]);
        if ((u >> 21) == b1) atomicAdd(&hL[(u >> 10) & 2047u], 1u);
    }
    __syncthreads();
    for (int i = tid; i < NB2; i += 256) {
        unsigned v = hL[i];
        if (v) atomicAdd(&g_h2[i], v);
    }
    gsync(1, nbk);
    unsigned b2; int k2;
    find_bucket_g<NB2>(g_h2, k1, csum, &s_b, &s_k, b2, k2);

    // ---------------- level 3 ------------------------------------------------
    for (int i = tid; i < NB3; i += 256) hL[i] = 0;
    __syncthreads();
    const unsigned pfx = (b1 << 11) | b2;
    for (int i = blockIdx.x * 256 + tid; i < n; i += stride) {
        unsigned u = orderf(g_loss[i]);
        if ((u >> 10) == pfx) atomicAdd(&hL[u & 1023u], 1u);
    }
    __syncthreads();
    for (int i = tid; i < NB3; i += 256) {
        unsigned v = hL[i];
        if (v) atomicAdd(&g_h3[i], v);
    }
    gsync(2, nbk);
    unsigned b3; int k3;
    find_bucket_g<NB3>(g_h3, k2, csum, &s_b, &s_k, b3, k3);
    const unsigned key = (pfx << 10) | b3;

    // ---------------- reduce: clean sum + masked correction ------------------
    {
        double cs = 0.0, crs = 0.0;
        unsigned long long cnt = 0ull;
        for (int i = blockIdx.x * 256 + tid; i < n; i += stride) {
            float L = g_loss[i];
            unsigned u = orderf(L);
            if (u <= key) {
                cs += (double)L;
            } else {
                float c = g_corr[i];
                if (c >= 0.0f) { crs += (double)c; cnt++; }
            }
        }
#pragma unroll
        for (int off = 16; off; off >>= 1) {
            cs  += __shfl_xor_sync(FULL, cs, off);
            crs += __shfl_xor_sync(FULL, crs, off);
            cnt += __shfl_xor_sync(FULL, cnt, off);
        }
        if (lane == 0) { skl[wid] = cs; sls[wid] = crs; scnt[wid] = cnt; }
        __syncthreads();
        if (tid == 0) {
            double a = 0.0, b = 0.0; unsigned long long c = 0ull;
#pragma unroll
            for (int w = 0; w < 8; w++) { a += skl[w]; b += sls[w]; c += scnt[w]; }
            atomicAdd(&g_clean_sum, a);
            atomicAdd(&g_corr_sum, b);
            atomicAdd(&g_cnt, c);
        }
    }
    gsync(3, nbk);

    // ---------------- finalize (block 0) -------------------------------------
    if (blockIdx.x == 0) {
        double kv = 0.0, lv = 0.0;
        for (unsigned i = tid; i < nbk; i += 256) { kv += g_kl_blk[i]; lv += g_ls_blk[i]; }
        dred[tid] = kv;
        __syncthreads();
        for (int off = 128; off; off >>= 1) {
            if (tid < off) dred[tid] += dred[tid + off];
            __syncthreads();
        }
        double klsum = dred[0];
        __syncthreads();
        dred[tid] = lv;
        __syncthreads();
        for (int off = 128; off; off >>= 1) {
            if (tid < off) dred[tid] += dred[tid + off];
            __syncthreads();
        }
        double lsum = dred[0];

        if (tid == 0) {
            double res;
            if (epoch == 0) {
                res = lsum / (double)n;
            } else {
                double clean = g_clean_sum / (double)kk;
                unsigned long long cc = g_cnt;
                double corrm = (cc > 0ull) ? (g_corr_sum / (double)cc) : 0.0;
                res = clean + corrm + 0.1 * (klsum / (double)n);
            }
            *out = (float)res;
        }
    }
}

// ---------------- launch ------------------------------------------------------
extern "C" void kernel_launch(void* const* d_in, const int* in_sizes, int n_in,
                              void* d_out, int out_size) {
    const float* y1   = (const float*)d_in[0];
    const float* y2   = (const float*)d_in[1];
    const void*  targ = d_in[2];
    const void*  ep   = d_in[3];
    int n = in_sizes[0] / C;

    int dev = 0;
    cudaGetDevice(&dev);
    int sms = 148;
    cudaDeviceGetAttribute(&sms, cudaDevAttrMultiProcessorCount, dev);
    int maxb = 1;
    cudaOccupancyMaxActiveBlocksPerMultiprocessor(&maxb, k_fused, 256, 0);
    if (maxb < 1) maxb = 1;
    int cap = sms * maxb;
    if (cap > MAXB) cap = MAXB;

    int ntiles = (n + TR - 1) / TR;
    if (cap > ntiles) cap = ntiles;
    int kper = (ntiles + cap - 1) / cap;          // tiles per block (ceil)
    int nb   = (ntiles + kper - 1) / kper;        // balanced block count
    if (nb < 1) nb = 1;

    k_init<<<1, 1024>>>(targ, n);
    k_fused<<<nb, 256>>>(y1, y2, targ, ep, n, (float*)d_out);
}